// round 13
// baseline (speedup 1.0000x reference)
#include <cuda_runtime.h>
#include <math.h>
#include <stdint.h>

#define BB 2
#define TT 2048
#define EE 2048
#define HH 16
#define HKV 8
#define DD 128
#define QTILE 128
#define KT32 32
#define NT32 (TT/KT32)      // 64 kv tiles
#define NCAT 4096           // fused QKV output columns
#define SCALE 0.08838834764831845f

// ---------------- scratch (static device globals; no allocation) ----------------
__device__ uint4    g_x4[BB*TT*EE/4];                 // packed-A x (tf32 bits)
__device__ uint4    g_wqkv4[EE/8*(NCAT/16)*8*4];      // packed-B wq|wk|wv (uint4 pairs)
__device__ uint4    g_wo4[HH*DD/8*(EE/16)*8*4];       // packed-B wo (uint4 pairs)
__device__ uint4    g_q4[BB*HH*TT*DD/4];              // packed-A Q (rope+scale, tf32)
__device__ uint32_t g_kx[BB*HKV*NT32*16*2*32*4];      // packed K uint4-pairs (4096 u32/tile)
__device__ uint32_t g_vf[BB*HKV*NT32*4*8*32*4];       // packed V uint4-pairs (4096 u32/tile)
__device__ uint4    g_attn4[BB*TT*HH*DD/4];           // packed-A attn (tf32)
__device__ float2   g_rope[TT*64];                    // per (t,j) {cos,sin}

__device__ __forceinline__ uint32_t f2tf(float x) {
    uint32_t u;
    asm("cvt.rna.tf32.f32 %0, %1;" : "=r"(u) : "f"(x));
    return u;
}

__device__ __forceinline__ void mma_tf32(float* d, const uint32_t* a, const uint32_t* b) {
    asm volatile(
        "mma.sync.aligned.m16n8k8.row.col.f32.tf32.tf32.f32 "
        "{%0,%1,%2,%3}, {%4,%5,%6,%7}, {%8,%9}, {%0,%1,%2,%3};"
        : "+f"(d[0]), "+f"(d[1]), "+f"(d[2]), "+f"(d[3])
        : "r"(a[0]), "r"(a[1]), "r"(a[2]), "r"(a[3]), "r"(b[0]), "r"(b[1]));
}

__device__ __forceinline__ void cp16(uint32_t saddr, const void* gptr) {
    asm volatile("cp.async.cg.shared.global [%0], [%1], 16;" :: "r"(saddr), "l"(gptr));
}

// ---------------- prepasses ----------------
__global__ void rope_init_kernel() {
    int i = blockIdx.x * 256 + threadIdx.x;     // < TT*64
    int j = i & 63, t = i >> 6;
    float inv = exp2f(-0.20762050593045952f * (float)j);  // 10000^(-j/64)
    float s, c;
    sincosf((float)t * inv, &s, &c);
    g_rope[i] = make_float2(c, s);
}

// x[4096][2048] -> packed-A uint4 fragments {(m,k),(m+8,k),(m,k+4),(m+8,k+4)}
__global__ void pack_x_kernel(const float* __restrict__ x) {
    int id = blockIdx.x * 256 + threadIdx.x;    // < 2097152
    int lc = id & 3, lr = (id >> 2) & 7, kg = (id >> 5) & 255, mb = id >> 13;
    const float* p = x + (size_t)(mb * 16 + lr) * 2048 + kg * 8 + lc;
    g_x4[id] = make_uint4(f2tf(p[0]), f2tf(p[8 * 2048]), f2tf(p[4]), f2tf(p[8 * 2048 + 4]));
}

// w[K=2048][Nsrc] -> packed-B uint4 pairs {(k,n),(k+4,n),(k,n+8),(k+4,n+8)}
// out4[((kg*(Ntot/16) + npg)*8 + r)*4 + lc], npg = noff/16 + npl, n = npg*16 + r (+8)
__global__ void pack_w_kernel(const float* __restrict__ w, uint4* __restrict__ out4,
                              int nsh, int Ntot, int noff) {
    int id = blockIdx.x * 256 + threadIdx.x;    // < 512 * Nsrc
    int Nsrc = 1 << nsh;
    int lc = id & 3, r = (id >> 2) & 7;
    int npl = (id >> 5) & ((Nsrc >> 4) - 1);
    int kg = id >> (nsh + 1);
    const float* p = w + (size_t)(kg * 8 + lc) * Nsrc + (npl << 4) + r;
    out4[(((size_t)kg * (Ntot >> 4) + (noff >> 4) + npl) * 8 + r) * 4 + lc] =
        make_uint4(f2tf(p[0]), f2tf(p[4 * Nsrc]), f2tf(p[8]), f2tf(p[4 * Nsrc + 8]));
}

// ---------------- 3-stage pipelined tf32 GEMM on pre-packed operands ----------------
// EPI: 0 plain fp32 store | 5 fused QKV epilogue (Q rope->g_q4, K rope->g_kx, V->g_vf)
template<int EPI>
__global__ __launch_bounds__(256, 2)
void gemm_kernel(const uint4* __restrict__ A4, const uint4* __restrict__ B4,
                 void* __restrict__ Cout, int M, int N, int K) {
    extern __shared__ uint32_t smu[];
    uint4* As4 = (uint4*)smu;                    // [3][1024] uint4 (16KB/stage)
    uint4* Bs4 = As4 + 3 * 1024;                 // [3][1024] uint4 (16KB/stage)

    const int tid  = threadIdx.x;
    const int brow = blockIdx.y * 128;
    const int bcol = blockIdx.x * 128;
    const int lane = tid & 31, warp = tid >> 5;
    const int wr = warp >> 2, wc = warp & 3;
    const int n_base = wc * 32;
    const int lr = lane >> 2, lc = lane & 3;
    const int KG = K >> 3;
    const int NP = N >> 4;

    float acc[4][4][4];
#pragma unroll
    for (int mt = 0; mt < 4; mt++)
#pragma unroll
        for (int nt = 0; nt < 4; nt++)
#pragma unroll
            for (int i = 0; i < 4; i++) acc[mt][nt][i] = 0.f;

    const uint32_t as_base = (uint32_t)__cvta_generic_to_shared(As4);
    const uint32_t bs_base = (uint32_t)__cvta_generic_to_shared(Bs4);

#define LOAD_TILE(K0, BUF)                                                              \
    {                                                                                   \
        const int kg0 = (K0) >> 3;                                                      \
        _Pragma("unroll")                                                               \
        for (int i = 0; i < 4; i++) {                                                   \
            int id = tid + i * 256;                                                     \
            int mb = id >> 7, sub = id & 127;                                           \
            cp16(as_base + ((BUF) * 1024 + mb * 128 + sub) * 16,                        \
                 A4 + ((size_t)((brow >> 4) + mb) * KG + kg0 + (sub >> 5)) * 32         \
                    + (sub & 31));                                                      \
            int kgl = id >> 8, off = id & 255;                                          \
            cp16(bs_base + ((BUF) * 1024 + kgl * 256 + off) * 16,                       \
                 B4 + ((size_t)(kg0 + kgl) * NP + (bcol >> 4)) * 32 + off);             \
        }                                                                               \
        asm volatile("cp.async.commit_group;");                                         \
    }

    const int NIT = K >> 5;     // 64
    LOAD_TILE(0, 0);
    LOAD_TILE(32, 1);

    for (int it = 0; it < NIT; it++) {
        if (it + 2 < NIT) {
            LOAD_TILE((it + 2) << 5, (it + 2) % 3);
            asm volatile("cp.async.wait_group 2;");
        } else if (it + 1 < NIT) {
            asm volatile("cp.async.wait_group 1;");
        } else {
            asm volatile("cp.async.wait_group 0;");
        }
        __syncthreads();

        const int buf = it % 3;
        const uint4* Ab = As4 + buf * 1024;
        const uint4* Bb = Bs4 + buf * 1024;
#pragma unroll
        for (int ks = 0; ks < 4; ks++) {
            uint4 afr[4], bfr4[2];
#pragma unroll
            for (int mt = 0; mt < 4; mt++)
                afr[mt] = Ab[(wr * 4 + mt) * 128 + ks * 32 + lane];
#pragma unroll
            for (int i = 0; i < 2; i++)
                bfr4[i] = Bb[ks * 256 + (wc * 2 + i) * 32 + lr * 4 + lc];
#pragma unroll
            for (int mt = 0; mt < 4; mt++) {
                mma_tf32(acc[mt][0], (const uint32_t*)&afr[mt], &bfr4[0].x);
                mma_tf32(acc[mt][1], (const uint32_t*)&afr[mt], &bfr4[0].z);
                mma_tf32(acc[mt][2], (const uint32_t*)&afr[mt], &bfr4[1].x);
                mma_tf32(acc[mt][3], (const uint32_t*)&afr[mt], &bfr4[1].z);
            }
        }
        __syncthreads();
    }

    // ---------------- epilogue ----------------
#pragma unroll
    for (int mt = 0; mt < 4; mt++)
#pragma unroll
        for (int nt = 0; nt < 4; nt++) {
            int row = brow + wr * 64 + mt * 16 + lr;
            int col = bcol + n_base + nt * 8 + 2 * lc;
            float c0 = acc[mt][nt][0], c1 = acc[mt][nt][1];
            float c2 = acc[mt][nt][2], c3 = acc[mt][nt][3];
            if (EPI == 0) {
                float* C = (float*)Cout;
                *(float2*)(C + (size_t)row * N + col)       = make_float2(c0, c1);
                *(float2*)(C + (size_t)(row + 8) * N + col) = make_float2(c2, c3);
            } else {
                int b = row >> 11, t = row & (TT - 1);
                if (col < 2048) {
                    // Q: rope + scale -> packed-A fragment layout (g_q4)
                    int h = col >> 7, j = (col & 127) >> 1;
                    float2 r1 = g_rope[t * 64 + j];
                    float2 r2 = g_rope[(t + 8) * 64 + j];
                    float va = (c0 * r1.x - c1 * r1.y) * SCALE;
                    float vb = (c1 * r1.x + c0 * r1.y) * SCALE;
                    float vc = (c2 * r2.x - c3 * r2.y) * SCALE;
                    float vd = (c3 * r2.x + c2 * r2.y) * SCALE;
                    uint32_t* W = (uint32_t*)g_q4;
                    size_t bh = (size_t)(b * HH + h) * 65536;
                    int mblk = t >> 4, lrq = t & 7;
#pragma unroll
                    for (int e = 0; e < 2; e++) {
                        int d = (e == 0) ? j : j + 64;
                        float vh0 = (e == 0) ? va : vb;
                        float vh1 = (e == 0) ? vc : vd;
                        size_t u4 = bh + (size_t)(mblk * 16 + (d >> 3)) * 32 + lrq * 4 + ((d & 7) & 3);
                        uint32_t* p = W + u4 * 4 + (((d & 7) >> 2) << 1);
                        *(uint2*)p = make_uint2(f2tf(vh0), f2tf(vh1));
                    }
                } else if (col < 3072) {
                    // K: rope -> packed uint4-pair layout (g_kx)
                    int colk = col - 2048;
                    int h = colk >> 7, j = (colk & 127) >> 1;
                    float2 r1 = g_rope[t * 64 + j];
                    float2 r2 = g_rope[(t + 8) * 64 + j];
                    float va = c0 * r1.x - c1 * r1.y;
                    float vb = c1 * r1.x + c0 * r1.y;
                    float vc = c2 * r2.x - c3 * r2.y;
                    float vd = c3 * r2.x + c2 * r2.y;
                    size_t bh = (size_t)(b * HKV + h) * NT32;
#pragma unroll
                    for (int e = 0; e < 4; e++) {
                        int tt = (e < 2) ? t : t + 8;
                        int d  = (e & 1) ? j + 64 : j;
                        float val = (e == 0) ? va : (e == 1) ? vb : (e == 2) ? vc : vd;
                        int tile = tt >> 5, r = tt & 31, kb = d >> 3, c = d & 7;
                        g_kx[(((((bh + tile) * 16 + kb) * 2 + (r >> 4)) * 32
                               + (r & 7) * 4 + (c & 3)) << 2)
                             + (c >> 2) + ((r >> 3) & 1) * 2] = f2tf(val);
                    }
                } else {
                    // V: packed uint4-pair layout (g_vf)
                    int colv = col - 3072;
                    int h = colv >> 7, d = colv & 127;
                    size_t bh = (size_t)(b * HKV + h) * NT32;
#pragma unroll
                    for (int e = 0; e < 4; e++) {
                        int tt = (e < 2) ? t : t + 8;
                        int dd = d + (e & 1);
                        float val = (e == 0) ? c0 : (e == 1) ? c1 : (e == 2) ? c2 : c3;
                        int tile = tt >> 5, s = tt & 31;
                        g_vf[((((((bh + tile) * 4 + (s >> 3)) * 8 + (dd >> 4)) * 32
                                + (dd & 7) * 4 + (s & 3)) << 2))
                             + ((s >> 2) & 1) + ((dd >> 3) & 1) * 2] = f2tf(val);
                    }
                }
            }
        }
}

// ---------------- Tensor-core flash attention (tf32 mma, causal) ----------------
// grid: (T/128, H, B); 256 threads (8 warps), 2 CTAs/SM, heavy tiles first.
// Q streamed from L2; K/V uint4-pair fragments; single tf32 mma; MUFU exp.
__global__ __launch_bounds__(256, 2)
void flash_kernel(const uint4* __restrict__ Q4, const uint32_t* __restrict__ KXg,
                  const uint32_t* __restrict__ VFg, uint4* __restrict__ Attn4) {
    extern __shared__ uint32_t smu[];
    uint32_t* KX = smu;                    // 2 x 4096  (packed K tile)
    uint32_t* VF = smu + 8192;             // 2 x 4096  (packed V tile)
    uint32_t* Ps = smu + 16384;            // 128 x 36  (tf32 P)

    const int tid = threadIdx.x;
    const int qt = gridDim.x - 1 - blockIdx.x;   // heavy (large-qt) blocks first
    const int h = blockIdx.y, b = blockIdx.z;
    const int q0 = qt * QTILE;
    const int hkv = h & (HKV - 1);
    const int warp = tid >> 5, lane = tid & 31;
    const int lr = lane >> 2, lc = lane & 3;
    const int m0 = warp * 16;
    const int ra = m0 + lr, rb = ra + 8;
    const int grow_a = q0 + ra, grow_b = q0 + rb;

    // g_q4 holds 65536 uint4 per (b,h): 128 m-blocks x 16 kb x 32 lanes
    const uint4*    Qb = Q4 + (size_t)(b * HH + h) * 65536 + (size_t)(qt * 8 + warp) * 512;
    const uint32_t* Kt = KXg + (size_t)(b * HKV + hkv) * NT32 * 4096;
    const uint32_t* Vt = VFg + (size_t)(b * HKV + hkv) * NT32 * 4096;

    const uint32_t kx_base = (uint32_t)__cvta_generic_to_shared(KX);
    const uint32_t vf_base = (uint32_t)__cvta_generic_to_shared(VF);

#define KV_ISSUE(KTT, BUF)                                                      \
    {                                                                           \
        _Pragma("unroll")                                                       \
        for (int i = 0; i < 4; i++) {                                           \
            int id = tid + i * 256;                                             \
            cp16(kx_base + ((BUF) * 4096 + id * 4) * 4,                         \
                 Kt + (size_t)(KTT) * 4096 + id * 4);                           \
            cp16(vf_base + ((BUF) * 4096 + id * 4) * 4,                         \
                 Vt + (size_t)(KTT) * 4096 + id * 4);                           \
        }                                                                       \
        asm volatile("cp.async.commit_group;");                                 \
    }

    const int nkt = 4 * (qt + 1);
    KV_ISSUE(0, 0);

    float O[16][4];
#pragma unroll
    for (int nb = 0; nb < 16; nb++)
#pragma unroll
        for (int i = 0; i < 4; i++) O[nb][i] = 0.f;
    float m_a = -1e30f, m_b = -1e30f, l_a = 0.f, l_b = 0.f;

    for (int kt = 0; kt < nkt; kt++) {
        asm volatile("cp.async.wait_group 0;");
        __syncthreads();
        if (kt + 1 < nkt) KV_ISSUE(kt + 1, (kt + 1) & 1);

        const uint4* Kb4 = (const uint4*)(KX + (kt & 1) * 4096);
        const uint4* Vb4 = (const uint4*)(VF + (kt & 1) * 4096);

        // ---- S = Q @ K^T (Q streamed from L2, K uint4-pair fragments) ----
        float S[4][4];
#pragma unroll
        for (int nb = 0; nb < 4; nb++)
#pragma unroll
            for (int i = 0; i < 4; i++) S[nb][i] = 0.f;

#pragma unroll
        for (int ks = 0; ks < 16; ks++) {
            uint4 qf = Qb[ks * 32 + lane];
            uint4 kf0 = Kb4[(ks * 2 + 0) * 32 + lr * 4 + lc];
            uint4 kf1 = Kb4[(ks * 2 + 1) * 32 + lr * 4 + lc];
            mma_tf32(S[0], (const uint32_t*)&qf, &kf0.x);
            mma_tf32(S[1], (const uint32_t*)&qf, &kf0.z);
            mma_tf32(S[2], (const uint32_t*)&qf, &kf1.x);
            mma_tf32(S[3], (const uint32_t*)&qf, &kf1.z);
        }

        // ---- causal mask (only diagonal-overlapping tiles) ----
        const int s0 = kt * KT32;
        if (kt >= 4 * qt) {
#pragma unroll
            for (int nb = 0; nb < 4; nb++) {
                int col = s0 + nb * 8 + 2 * lc;
                if (col     > grow_a) S[nb][0] = -1e30f;
                if (col + 1 > grow_a) S[nb][1] = -1e30f;
                if (col     > grow_b) S[nb][2] = -1e30f;
                if (col + 1 > grow_b) S[nb][3] = -1e30f;
            }
        }

        // ---- online softmax (MUFU exp) ----
        float mxa = m_a, mxb = m_b;
#pragma unroll
        for (int nb = 0; nb < 4; nb++) {
            mxa = fmaxf(mxa, fmaxf(S[nb][0], S[nb][1]));
            mxb = fmaxf(mxb, fmaxf(S[nb][2], S[nb][3]));
        }
        mxa = fmaxf(mxa, __shfl_xor_sync(0xffffffffu, mxa, 1));
        mxa = fmaxf(mxa, __shfl_xor_sync(0xffffffffu, mxa, 2));
        mxb = fmaxf(mxb, __shfl_xor_sync(0xffffffffu, mxb, 1));
        mxb = fmaxf(mxb, __shfl_xor_sync(0xffffffffu, mxb, 2));

        float corr_a = __expf(m_a - mxa);
        float corr_b = __expf(m_b - mxb);
        m_a = mxa; m_b = mxb;

        float suma = 0.f, sumb = 0.f;
#pragma unroll
        for (int nb = 0; nb < 4; nb++) {
            float p0 = __expf(S[nb][0] - mxa);
            float p1 = __expf(S[nb][1] - mxa);
            float p2 = __expf(S[nb][2] - mxb);
            float p3 = __expf(S[nb][3] - mxb);
            suma += p0 + p1;
            sumb += p2 + p3;
            *(uint2*)(Ps + ra * 36 + nb * 8 + 2 * lc) = make_uint2(f2tf(p0), f2tf(p1));
            *(uint2*)(Ps + rb * 36 + nb * 8 + 2 * lc) = make_uint2(f2tf(p2), f2tf(p3));
        }
        suma += __shfl_xor_sync(0xffffffffu, suma, 1);
        suma += __shfl_xor_sync(0xffffffffu, suma, 2);
        sumb += __shfl_xor_sync(0xffffffffu, sumb, 1);
        sumb += __shfl_xor_sync(0xffffffffu, sumb, 2);
        l_a = l_a * corr_a + suma;
        l_b = l_b * corr_b + sumb;

#pragma unroll
        for (int nb = 0; nb < 16; nb++) {
            O[nb][0] *= corr_a; O[nb][1] *= corr_a;
            O[nb][2] *= corr_b; O[nb][3] *= corr_b;
        }
        __syncwarp();    // P is warp-private (rows of this warp only)

        // ---- O += P @ V (V uint4-pair fragments) ----
#pragma unroll
        for (int ks = 0; ks < 4; ks++) {
            const int k0 = ks * 8;
            uint32_t a[4] = { Ps[ra * 36 + k0 + lc],
                              Ps[rb * 36 + k0 + lc],
                              Ps[ra * 36 + k0 + lc + 4],
                              Ps[rb * 36 + k0 + lc + 4] };
#pragma unroll
            for (int nbp = 0; nbp < 8; nbp++) {
                uint4 vv = Vb4[(ks * 8 + nbp) * 32 + lr * 4 + lc];
                mma_tf32(O[2 * nbp],     a, &vv.x);
                mma_tf32(O[2 * nbp + 1], a, &vv.z);
            }
        }
    }

    // ---- epilogue: normalize + write packed-A attn (tf32 bits) ----
    float inva = 1.0f / l_a, invb = 1.0f / l_b;
    uint32_t* attnW = (uint32_t*)Attn4;
    const int mblk = b * 128 + qt * 8 + warp;
    const int lcp0 = (2 * lc) & 3, lcp1 = (2 * lc + 1) & 3;
    const int hi2  = ((2 * lc) >> 2) << 1;
#pragma unroll
    for (int nb = 0; nb < 16; nb++) {
        size_t sb = ((size_t)(mblk * 256 + h * 16 + nb) * 8 + lr) * 16;
        *(uint2*)(attnW + sb + lcp0 * 4 + hi2) =
            make_uint2(f2tf(O[nb][0] * inva), f2tf(O[nb][2] * invb));
        *(uint2*)(attnW + sb + lcp1 * 4 + hi2) =
            make_uint2(f2tf(O[nb][1] * inva), f2tf(O[nb][3] * invb));
    }
}

// ---------------- launch ----------------
extern "C" void kernel_launch(void* const* d_in, const int* in_sizes, int n_in,
                              void* d_out, int out_size) {
    const float* x  = (const float*)d_in[0];
    const float* wq = (const float*)d_in[2];
    const float* wk = (const float*)d_in[3];
    const float* wv = (const float*)d_in[4];
    const float* wo = (const float*)d_in[5];
    float* out = (float*)d_out;

    uint4 *x4, *wqkv4, *wo4, *q4, *attn4;
    uint32_t *kx, *vf;
    cudaGetSymbolAddress((void**)&x4,    g_x4);
    cudaGetSymbolAddress((void**)&wqkv4, g_wqkv4);
    cudaGetSymbolAddress((void**)&wo4,   g_wo4);
    cudaGetSymbolAddress((void**)&q4,    g_q4);
    cudaGetSymbolAddress((void**)&kx,    g_kx);
    cudaGetSymbolAddress((void**)&vf,    g_vf);
    cudaGetSymbolAddress((void**)&attn4, g_attn4);

    const int M = BB * TT;    // 4096
    const size_t gsmem = 98304;   // 3 stages x (16KB A + 16KB B)

    cudaFuncSetAttribute(gemm_kernel<0>, cudaFuncAttributeMaxDynamicSharedMemorySize, (int)gsmem);
    cudaFuncSetAttribute(gemm_kernel<5>, cudaFuncAttributeMaxDynamicSharedMemorySize, (int)gsmem);

    // prepasses: rope table + operand packing (tf32 rounding done once)
    rope_init_kernel<<<TT * 64 / 256, 256>>>();
    pack_x_kernel<<<BB * TT * EE / 4 / 256, 256>>>(x);
    pack_w_kernel<<<2 * 2048, 256>>>(wq, wqkv4, 11, NCAT, 0);
    pack_w_kernel<<<2 * 1024, 256>>>(wk, wqkv4, 10, NCAT, 2048);
    pack_w_kernel<<<2 * 1024, 256>>>(wv, wqkv4, 10, NCAT, 3072);
    pack_w_kernel<<<2 * 2048, 256>>>(wo, wo4, 11, EE, 0);

    // Fused QKV projection (one launch, epilogue dispatched by column block)
    gemm_kernel<5><<<dim3(NCAT/128, M/128), 256, gsmem>>>(x4, wqkv4, nullptr, M, NCAT, EE);

    // Flash attention (82 KB dynamic smem, 2 CTAs/SM)
    {
        size_t smem = (8192 + 8192 + 4608) * sizeof(uint32_t);  // 83968 B
        cudaFuncSetAttribute(flash_kernel, cudaFuncAttributeMaxDynamicSharedMemorySize, (int)smem);
        flash_kernel<<<dim3(TT/QTILE, HH, BB), 256, smem>>>(q4, kx, vf, attn4);
    }

    // Output projection (packed attn, plain fp32 store)
    gemm_kernel<0><<<dim3(EE/128, M/128), 256, gsmem>>>(attn4, wo4, out, M, EE, EE);
}

// round 14
// speedup vs baseline: 1.9022x; 1.9022x over previous
#include <cuda_runtime.h>
#include <cuda_fp16.h>
#include <math.h>
#include <stdint.h>

#define BB 2
#define TT 2048
#define EE 2048
#define HH 16
#define HKV 8
#define DD 128
#define QTILE 128
#define KT32 32
#define NT32 (TT/KT32)      // 64 kv tiles
#define NCAT 4096           // fused QKV output columns
#define PS_ST 20            // P smem row stride (u32/half2) - conflict-free
#define SCALE 0.08838834764831845f

// ---------------- scratch (static device globals; no allocation) ----------------
__device__ uint4    g_x4[BB*TT*EE/8];                 // packed-A x (fp16 m16n8k16 frags)
__device__ uint4    g_wqkv4[EE/16*(NCAT/16)*32];      // packed-B wq|wk|wv (uint4 n-pairs)
__device__ uint4    g_wo4[EE/16*(EE/16)*32];          // packed-B wo
__device__ uint4    g_q4[BB*HH*TT*DD/8];              // packed-A Q (rope+scale, fp16)
__device__ uint32_t g_kx[BB*HKV*NT32*2048];           // packed K fp16 B-frag pairs (8KB/tile)
__device__ uint32_t g_vf[BB*HKV*NT32*2048];           // packed V fp16 B-frag pairs (8KB/tile)
__device__ uint4    g_attn4[BB*TT*HH*DD/8];           // packed-A attn (fp16)
__device__ float2   g_rope[TT*64];                    // per (t,j) {cos,sin}

__device__ __forceinline__ uint32_t f2h2(float lo, float hi) {
    __half2 h = __floats2half2_rn(lo, hi);
    return *(uint32_t*)&h;
}

__device__ __forceinline__ void mma_f16(float* d, const uint32_t* a, const uint32_t* b) {
    asm volatile(
        "mma.sync.aligned.m16n8k16.row.col.f32.f16.f16.f32 "
        "{%0,%1,%2,%3}, {%4,%5,%6,%7}, {%8,%9}, {%0,%1,%2,%3};"
        : "+f"(d[0]), "+f"(d[1]), "+f"(d[2]), "+f"(d[3])
        : "r"(a[0]), "r"(a[1]), "r"(a[2]), "r"(a[3]), "r"(b[0]), "r"(b[1]));
}

__device__ __forceinline__ void cp16(uint32_t saddr, const void* gptr) {
    asm volatile("cp.async.cg.shared.global [%0], [%1], 16;" :: "r"(saddr), "l"(gptr));
}

// ---------------- prepasses ----------------
__global__ void rope_init_kernel() {
    int i = blockIdx.x * 256 + threadIdx.x;     // < TT*64
    int j = i & 63, t = i >> 6;
    float inv = exp2f(-0.20762050593045952f * (float)j);  // 10000^(-j/64)
    float s, c;
    sincosf((float)t * inv, &s, &c);
    g_rope[i] = make_float2(c, s);
}

// x[4096][2048] -> packed-A fp16 frags: uint4 per (mb, kg, lane)
// regs: a0={(r,2lc),(r,2lc+1)} a1={(r+8,..)} a2={(r,2lc+8),(r,2lc+9)} a3={(r+8,+8..)}
__global__ void pack_x_kernel(const float* __restrict__ x) {
    int id = blockIdx.x * 256 + threadIdx.x;    // < 1048576
    int lane = id & 31, kg = (id >> 5) & 127, mb = id >> 12;
    int r = lane >> 2, lc = lane & 3;
    const float* p = x + (size_t)(mb * 16 + r) * 2048 + kg * 16 + 2 * lc;
    float2 v00 = *(const float2*)(p);
    float2 v01 = *(const float2*)(p + 8);
    float2 v10 = *(const float2*)(p + 8 * 2048);
    float2 v11 = *(const float2*)(p + 8 * 2048 + 8);
    g_x4[id] = make_uint4(f2h2(v00.x, v00.y), f2h2(v10.x, v10.y),
                          f2h2(v01.x, v01.y), f2h2(v11.x, v11.y));
}

// w[K=2048][Nsrc] -> packed-B fp16 uint4 n-pairs:
// {b0(n),b1(n), b0(n+8),b1(n+8)}; b0={(2lc,n),(2lc+1,n)} b1={(2lc+8,n),(2lc+9,n)}
__global__ void pack_w_kernel(const float* __restrict__ w, uint4* __restrict__ out4,
                              int nsh, int Ntot, int noff) {
    int id = blockIdx.x * 256 + threadIdx.x;    // < 128 * (Nsrc/16) * 32
    int Nsrc = 1 << nsh;
    int lane = id & 31;
    int npl = (id >> 5) & ((Nsrc >> 4) - 1);
    int kg = id >> (nsh + 1);
    int r = lane >> 2, lc = lane & 3;
    const float* p = w + (size_t)(kg * 16 + 2 * lc) * Nsrc + npl * 16 + r;
    float a0 = p[0],        a1 = p[Nsrc];
    float a2 = p[8 * Nsrc], a3 = p[9 * Nsrc];
    float b0 = p[8],        b1 = p[Nsrc + 8];
    float b2 = p[8 * Nsrc + 8], b3 = p[9 * Nsrc + 8];
    out4[((size_t)kg * (Ntot >> 4) + (noff >> 4) + npl) * 32 + lane] =
        make_uint4(f2h2(a0, a1), f2h2(a2, a3), f2h2(b0, b1), f2h2(b2, b3));
}

// ---------------- 2-stage pipelined fp16 GEMM on pre-packed operands ----------------
// EPI: 0 plain fp32 store | 5 fused QKV epilogue (Q->g_q4, K->g_kx, V->g_vf)
template<int EPI>
__global__ __launch_bounds__(256, 2)
void gemm_kernel(const uint4* __restrict__ A4, const uint4* __restrict__ B4,
                 void* __restrict__ Cout, int M, int N, int K) {
    extern __shared__ uint32_t smu[];
    uint4* As4 = (uint4*)smu;                    // [2][1024] uint4 (16KB/stage)
    uint4* Bs4 = As4 + 2 * 1024;                 // [2][1024] uint4 (16KB/stage)

    const int tid  = threadIdx.x;
    const int brow = blockIdx.y * 128;
    const int bcol = blockIdx.x * 128;
    const int lane = tid & 31, warp = tid >> 5;
    const int wr = warp >> 2, wc = warp & 3;
    const int n_base = wc * 32;
    const int lr = lane >> 2, lc = lane & 3;
    const int KG16 = K >> 4;

    float acc[4][4][4];
#pragma unroll
    for (int mt = 0; mt < 4; mt++)
#pragma unroll
        for (int nt = 0; nt < 4; nt++)
#pragma unroll
            for (int i = 0; i < 4; i++) acc[mt][nt][i] = 0.f;

    const uint32_t as_base = (uint32_t)__cvta_generic_to_shared(As4);
    const uint32_t bs_base = (uint32_t)__cvta_generic_to_shared(Bs4);

#define LOAD_TILE(K0, BUF)                                                              \
    {                                                                                   \
        const int kg0 = (K0) >> 4;                                                      \
        _Pragma("unroll")                                                               \
        for (int i = 0; i < 4; i++) {                                                   \
            int id = tid + i * 256;                                                     \
            int mb = id >> 7, sub = id & 127;                                           \
            cp16(as_base + ((BUF) * 1024 + mb * 128 + sub) * 16,                        \
                 A4 + ((size_t)((brow >> 4) + mb) * KG16 + kg0 + (sub >> 5)) * 32       \
                    + (sub & 31));                                                      \
            int kgl = id >> 8, off = id & 255;                                          \
            cp16(bs_base + ((BUF) * 1024 + kgl * 256 + off) * 16,                       \
                 B4 + ((size_t)(kg0 + kgl) * (N >> 4) + (bcol >> 4)) * 32 + off);       \
        }                                                                               \
        asm volatile("cp.async.commit_group;");                                         \
    }

    const int NIT = K >> 6;     // BK=64
    LOAD_TILE(0, 0);

    for (int it = 0; it < NIT; it++) {
        if (it + 1 < NIT) {
            LOAD_TILE((it + 1) << 6, (it + 1) & 1);
            asm volatile("cp.async.wait_group 1;");
        } else {
            asm volatile("cp.async.wait_group 0;");
        }
        __syncthreads();

        const uint4* Ab = As4 + (it & 1) * 1024;
        const uint4* Bb = Bs4 + (it & 1) * 1024;
#pragma unroll
        for (int ks = 0; ks < 4; ks++) {
            uint4 afr[4], bfr4[2];
#pragma unroll
            for (int mt = 0; mt < 4; mt++)
                afr[mt] = Ab[(wr * 4 + mt) * 128 + ks * 32 + lane];
#pragma unroll
            for (int i = 0; i < 2; i++)
                bfr4[i] = Bb[ks * 256 + (wc * 2 + i) * 32 + lane];
#pragma unroll
            for (int mt = 0; mt < 4; mt++) {
                mma_f16(acc[mt][0], &afr[mt].x, &bfr4[0].x);
                mma_f16(acc[mt][1], &afr[mt].x, &bfr4[0].z);
                mma_f16(acc[mt][2], &afr[mt].x, &bfr4[1].x);
                mma_f16(acc[mt][3], &afr[mt].x, &bfr4[1].z);
            }
        }
        __syncthreads();
    }

    // ---------------- epilogue ----------------
#pragma unroll
    for (int mt = 0; mt < 4; mt++)
#pragma unroll
        for (int nt = 0; nt < 4; nt++) {
            int row = brow + wr * 64 + mt * 16 + lr;
            int col = bcol + n_base + nt * 8 + 2 * lc;
            float c0 = acc[mt][nt][0], c1 = acc[mt][nt][1];
            float c2 = acc[mt][nt][2], c3 = acc[mt][nt][3];
            if (EPI == 0) {
                float* C = (float*)Cout;
                *(float2*)(C + (size_t)row * N + col)       = make_float2(c0, c1);
                *(float2*)(C + (size_t)(row + 8) * N + col) = make_float2(c2, c3);
            } else {
                int b = row >> 11, t = row & (TT - 1);
                if (col < 2048) {
                    // Q: rope + scale -> packed-A fp16 fragment layout (g_q4)
                    int h = col >> 7, j = (col & 127) >> 1;
                    float2 r1 = g_rope[t * 64 + j];
                    float2 r2 = g_rope[(t + 8) * 64 + j];
                    float va = (c0 * r1.x - c1 * r1.y) * SCALE;   // (t,   j)
                    float vb = (c1 * r1.x + c0 * r1.y) * SCALE;   // (t,   j+64)
                    float vc = (c2 * r2.x - c3 * r2.y) * SCALE;   // (t+8, j)
                    float vd = (c3 * r2.x + c2 * r2.y) * SCALE;   // (t+8, j+64)
                    __half* W = (__half*)g_q4 + (size_t)(b * HH + h) * 262144;
#pragma unroll
                    for (int e = 0; e < 4; e++) {
                        int tt = (e < 2) ? t : t + 8;
                        int d  = (e & 1) ? j + 64 : j;
                        float val = (e == 0) ? va : (e == 1) ? vb : (e == 2) ? vc : vd;
                        int mblk = tt >> 4, rr = tt & 7, m8 = (tt >> 3) & 1;
                        int kg = d >> 4, dd = d & 15;
                        int idx = (((mblk * 8 + kg) * 32) + rr * 4 + ((dd >> 1) & 3)) * 8
                                  + (m8 + 2 * (dd >> 3)) * 2 + (dd & 1);
                        W[idx] = __float2half_rn(val);
                    }
                } else if (col < 3072) {
                    // K: rope -> packed fp16 B-frag pair layout (g_kx)
                    int colk = col - 2048;
                    int h = colk >> 7, j = (colk & 127) >> 1;
                    float2 r1 = g_rope[t * 64 + j];
                    float2 r2 = g_rope[(t + 8) * 64 + j];
                    float va = c0 * r1.x - c1 * r1.y;
                    float vb = c1 * r1.x + c0 * r1.y;
                    float vc = c2 * r2.x - c3 * r2.y;
                    float vd = c3 * r2.x + c2 * r2.y;
                    __half* W = (__half*)g_kx + (size_t)(b * HKV + h) * NT32 * 4096;
#pragma unroll
                    for (int e = 0; e < 4; e++) {
                        int tt = (e < 2) ? t : t + 8;
                        int d  = (e & 1) ? j + 64 : j;
                        float val = (e == 0) ? va : (e == 1) ? vb : (e == 2) ? vc : vd;
                        int tile = tt >> 5, s = tt & 31;
                        int sp = s >> 4, rr = s & 7, s8 = (s >> 3) & 1;
                        int kg = d >> 4, dd = d & 15;
                        int idx = tile * 4096
                                  + (((kg * 2 + sp) * 32) + rr * 4 + ((dd >> 1) & 3)) * 8
                                  + s8 * 4 + (dd >> 3) * 2 + (dd & 1);
                        W[idx] = __float2half_rn(val);
                    }
                } else {
                    // V: packed fp16 B-frag pair layout (g_vf); n-dim = d, k-dim = s
                    int colv = col - 3072;
                    int h = colv >> 7, d = colv & 127;
                    __half* W = (__half*)g_vf + (size_t)(b * HKV + h) * NT32 * 4096;
#pragma unroll
                    for (int e = 0; e < 4; e++) {
                        int tt = (e < 2) ? t : t + 8;
                        int dd = d + (e & 1);
                        float val = (e == 0) ? c0 : (e == 1) ? c1 : (e == 2) ? c2 : c3;
                        int tile = tt >> 5, s = tt & 31;
                        int ks = s >> 4, ss = s & 15;
                        int np = dd >> 4, rv = dd & 7, d8 = (dd >> 3) & 1;
                        int idx = tile * 4096
                                  + ((ks * 8 + np) * 32 + rv * 4 + ((ss >> 1) & 3)) * 8
                                  + d8 * 4 + ((ss >> 3) & 1) * 2 + (ss & 1);
                        W[idx] = __float2half_rn(val);
                    }
                }
            }
        }
}

// ---------------- Tensor-core flash attention (fp16 mma, causal) ----------------
// grid: (T/128, H, B); 256 threads (8 warps), 2 CTAs/SM, heavy tiles first.
// Q streamed from L2 (fp16 A-frags); K/V fp16 B-frag pairs; MUFU exp.
__global__ __launch_bounds__(256, 2)
void flash_kernel(const uint4* __restrict__ Q4, const uint32_t* __restrict__ KXg,
                  const uint32_t* __restrict__ VFg, uint4* __restrict__ Attn4) {
    extern __shared__ uint32_t smu[];
    uint32_t* KX = smu;                    // 2 x 2048  (packed K tile, 8KB each)
    uint32_t* VF = smu + 4096;             // 2 x 2048  (packed V tile)
    uint32_t* Ps = smu + 8192;             // 128 x PS_ST (half2 P)

    const int tid = threadIdx.x;
    const int qt = gridDim.x - 1 - blockIdx.x;   // heavy (large-qt) blocks first
    const int h = blockIdx.y, b = blockIdx.z;
    const int q0 = qt * QTILE;
    const int hkv = h & (HKV - 1);
    const int warp = tid >> 5, lane = tid & 31;
    const int lr = lane >> 2, lc = lane & 3;
    const int m0 = warp * 16;
    const int ra = m0 + lr, rb = ra + 8;
    const int grow_a = q0 + ra, grow_b = q0 + rb;

    // g_q4: 32768 uint4 per (b,h) = 128 mblk x 8 kg x 32 lanes
    const uint4*    Qb = Q4 + (size_t)(b * HH + h) * 32768 + (size_t)(qt * 8 + warp) * 256;
    const uint32_t* Kt = KXg + (size_t)(b * HKV + hkv) * NT32 * 2048;
    const uint32_t* Vt = VFg + (size_t)(b * HKV + hkv) * NT32 * 2048;

    const uint32_t kx_base = (uint32_t)__cvta_generic_to_shared(KX);
    const uint32_t vf_base = (uint32_t)__cvta_generic_to_shared(VF);

#define KV_ISSUE(KTT, BUF)                                                      \
    {                                                                           \
        _Pragma("unroll")                                                       \
        for (int i = 0; i < 2; i++) {                                           \
            int id = tid + i * 256;                                             \
            cp16(kx_base + ((BUF) * 2048 + id * 4) * 4,                         \
                 Kt + (size_t)(KTT) * 2048 + id * 4);                           \
            cp16(vf_base + ((BUF) * 2048 + id * 4) * 4,                         \
                 Vt + (size_t)(KTT) * 2048 + id * 4);                           \
        }                                                                       \
        asm volatile("cp.async.commit_group;");                                 \
    }

    const int nkt = 4 * (qt + 1);
    KV_ISSUE(0, 0);

    float O[16][4];
#pragma unroll
    for (int nb = 0; nb < 16; nb++)
#pragma unroll
        for (int i = 0; i < 4; i++) O[nb][i] = 0.f;
    float m_a = -1e30f, m_b = -1e30f, l_a = 0.f, l_b = 0.f;

    for (int kt = 0; kt < nkt; kt++) {
        asm volatile("cp.async.wait_group 0;");
        __syncthreads();
        if (kt + 1 < nkt) KV_ISSUE(kt + 1, (kt + 1) & 1);

        const uint4* Kb4 = (const uint4*)(KX + (kt & 1) * 2048);
        const uint4* Vb4 = (const uint4*)(VF + (kt & 1) * 2048);

        // ---- S = Q @ K^T (fp16 k16, 8 k-steps over D=128) ----
        float S[4][4];
#pragma unroll
        for (int nb = 0; nb < 4; nb++)
#pragma unroll
            for (int i = 0; i < 4; i++) S[nb][i] = 0.f;

#pragma unroll
        for (int ks = 0; ks < 8; ks++) {
            uint4 qf  = Qb[ks * 32 + lane];
            uint4 kf0 = Kb4[(ks * 2 + 0) * 32 + lane];
            uint4 kf1 = Kb4[(ks * 2 + 1) * 32 + lane];
            mma_f16(S[0], &qf.x, &kf0.x);
            mma_f16(S[1], &qf.x, &kf0.z);
            mma_f16(S[2], &qf.x, &kf1.x);
            mma_f16(S[3], &qf.x, &kf1.z);
        }

        // ---- causal mask (only diagonal-overlapping tiles) ----
        const int s0 = kt * KT32;
        if (kt >= 4 * qt) {
#pragma unroll
            for (int nb = 0; nb < 4; nb++) {
                int col = s0 + nb * 8 + 2 * lc;
                if (col     > grow_a) S[nb][0] = -1e30f;
                if (col + 1 > grow_a) S[nb][1] = -1e30f;
                if (col     > grow_b) S[nb][2] = -1e30f;
                if (col + 1 > grow_b) S[nb][3] = -1e30f;
            }
        }

        // ---- online softmax (MUFU exp) ----
        float mxa = m_a, mxb = m_b;
#pragma unroll
        for (int nb = 0; nb < 4; nb++) {
            mxa = fmaxf(mxa, fmaxf(S[nb][0], S[nb][1]));
            mxb = fmaxf(mxb, fmaxf(S[nb][2], S[nb][3]));
        }
        mxa = fmaxf(mxa, __shfl_xor_sync(0xffffffffu, mxa, 1));
        mxa = fmaxf(mxa, __shfl_xor_sync(0xffffffffu, mxa, 2));
        mxb = fmaxf(mxb, __shfl_xor_sync(0xffffffffu, mxb, 1));
        mxb = fmaxf(mxb, __shfl_xor_sync(0xffffffffu, mxb, 2));

        float corr_a = __expf(m_a - mxa);
        float corr_b = __expf(m_b - mxb);
        m_a = mxa; m_b = mxb;

        float suma = 0.f, sumb = 0.f;
#pragma unroll
        for (int nb = 0; nb < 4; nb++) {
            float p0 = __expf(S[nb][0] - mxa);
            float p1 = __expf(S[nb][1] - mxa);
            float p2 = __expf(S[nb][2] - mxb);
            float p3 = __expf(S[nb][3] - mxb);
            suma += p0 + p1;
            sumb += p2 + p3;
            Ps[ra * PS_ST + nb * 4 + lc] = f2h2(p0, p1);
            Ps[rb * PS_ST + nb * 4 + lc] = f2h2(p2, p3);
        }
        suma += __shfl_xor_sync(0xffffffffu, suma, 1);
        suma += __shfl_xor_sync(0xffffffffu, suma, 2);
        sumb += __shfl_xor_sync(0xffffffffu, sumb, 1);
        sumb += __shfl_xor_sync(0xffffffffu, sumb, 2);
        l_a = l_a * corr_a + suma;
        l_b = l_b * corr_b + sumb;

#pragma unroll
        for (int nb = 0; nb < 16; nb++) {
            O[nb][0] *= corr_a; O[nb][1] *= corr_a;
            O[nb][2] *= corr_b; O[nb][3] *= corr_b;
        }
        __syncwarp();    // P is warp-private (rows of this warp only)

        // ---- O += P @ V (fp16 k16, 2 k-steps over s=32) ----
#pragma unroll
        for (int ks = 0; ks < 2; ks++) {
            uint32_t a[4] = { Ps[ra * PS_ST + ks * 8 + lc],
                              Ps[rb * PS_ST + ks * 8 + lc],
                              Ps[ra * PS_ST + ks * 8 + lc + 4],
                              Ps[rb * PS_ST + ks * 8 + lc + 4] };
#pragma unroll
            for (int np = 0; np < 8; np++) {
                uint4 vv = Vb4[(ks * 8 + np) * 32 + lane];
                mma_f16(O[2 * np],     a, &vv.x);
                mma_f16(O[2 * np + 1], a, &vv.z);
            }
        }
    }

    // ---- epilogue: normalize + write packed-A fp16 attn ----
    float inva = 1.0f / l_a, invb = 1.0f / l_b;
    uint32_t* attnW = (uint32_t*)Attn4;
    const int mblk = b * 128 + qt * 8 + warp;
#pragma unroll
    for (int nb = 0; nb < 16; nb++) {
        int kg  = h * 8 + (nb >> 1);
        int khi = nb & 1;
        size_t u4i = ((size_t)mblk * 128 + kg) * 32 + lr * 4 + lc;
        attnW[u4i * 4 + 0 + 2 * khi] = f2h2(O[nb][0] * inva, O[nb][1] * inva);
        attnW[u4i * 4 + 1 + 2 * khi] = f2h2(O[nb][2] * invb, O[nb][3] * invb);
    }
}

// ---------------- launch ----------------
extern "C" void kernel_launch(void* const* d_in, const int* in_sizes, int n_in,
                              void* d_out, int out_size) {
    const float* x  = (const float*)d_in[0];
    const float* wq = (const float*)d_in[2];
    const float* wk = (const float*)d_in[3];
    const float* wv = (const float*)d_in[4];
    const float* wo = (const float*)d_in[5];
    float* out = (float*)d_out;

    uint4 *x4, *wqkv4, *wo4, *q4, *attn4;
    uint32_t *kx, *vf;
    cudaGetSymbolAddress((void**)&x4,    g_x4);
    cudaGetSymbolAddress((void**)&wqkv4, g_wqkv4);
    cudaGetSymbolAddress((void**)&wo4,   g_wo4);
    cudaGetSymbolAddress((void**)&q4,    g_q4);
    cudaGetSymbolAddress((void**)&kx,    g_kx);
    cudaGetSymbolAddress((void**)&vf,    g_vf);
    cudaGetSymbolAddress((void**)&attn4, g_attn4);

    const int M = BB * TT;    // 4096
    const size_t gsmem = 65536;   // 2 stages x (16KB A + 16KB B)

    cudaFuncSetAttribute(gemm_kernel<0>, cudaFuncAttributeMaxDynamicSharedMemorySize, (int)gsmem);
    cudaFuncSetAttribute(gemm_kernel<5>, cudaFuncAttributeMaxDynamicSharedMemorySize, (int)gsmem);

    // prepasses: rope table + fp16 operand packing (rounding done once)
    rope_init_kernel<<<TT * 64 / 256, 256>>>();
    pack_x_kernel<<<BB * TT * EE / 8 / 256, 256>>>(x);
    pack_w_kernel<<<2048, 256>>>(wq, wqkv4, 11, NCAT, 0);
    pack_w_kernel<<<1024, 256>>>(wk, wqkv4, 10, NCAT, 2048);
    pack_w_kernel<<<1024, 256>>>(wv, wqkv4, 10, NCAT, 3072);
    pack_w_kernel<<<2048, 256>>>(wo, wo4, 11, EE, 0);

    // Fused QKV projection (one launch, epilogue dispatched by column block)
    gemm_kernel<5><<<dim3(NCAT/128, M/128), 256, gsmem>>>(x4, wqkv4, nullptr, M, NCAT, EE);

    // Flash attention (42 KB dynamic smem, 2 CTAs/SM)
    {
        size_t smem = (8192 + 128 * PS_ST) * sizeof(uint32_t);  // 43008 B
        cudaFuncSetAttribute(flash_kernel, cudaFuncAttributeMaxDynamicSharedMemorySize, (int)smem);
        flash_kernel<<<dim3(TT/QTILE, HH, BB), 256, smem>>>(q4, kx, vf, attn4);
    }

    // Output projection (packed fp16 attn, plain fp32 store)
    gemm_kernel<0><<<dim3(EE/128, M/128), 256, gsmem>>>(attn4, wo4, out, M, EE, EE);
}

// round 15
// speedup vs baseline: 1.9402x; 1.0200x over previous
#include <cuda_runtime.h>
#include <cuda_fp16.h>
#include <math.h>
#include <stdint.h>

#define BB 2
#define TT 2048
#define EE 2048
#define HH 16
#define HKV 8
#define DD 128
#define QTILE 128
#define KT32 32
#define NT32 (TT/KT32)      // 64 kv tiles
#define NCAT 4096           // fused QKV output columns
#define PS_ST 20            // P smem row stride (u32/half2) - conflict-free
#define SCALE 0.08838834764831845f

// ---------------- scratch (static device globals; no allocation) ----------------
__device__ uint4    g_x4[BB*TT*EE/8];                 // packed-A x (fp16 m16n8k16 frags)
__device__ uint4    g_wqkv4[EE/16*(NCAT/16)*32];      // packed-B wq|wk|wv (uint4 n-pairs)
__device__ uint4    g_wo4[EE/16*(EE/16)*32];          // packed-B wo
__device__ uint4    g_q4[BB*HH*TT*DD/8];              // packed-A Q (rope+scale, fp16)
__device__ uint32_t g_kx[BB*HKV*NT32*2048];           // packed K fp16 B-frag pairs (8KB/tile)
__device__ uint32_t g_vf[BB*HKV*NT32*2048];           // packed V fp16 B-frag pairs (8KB/tile)
__device__ uint4    g_attn4[BB*TT*HH*DD/8];           // packed-A attn (fp16)
__device__ float2   g_rope[TT*64];                    // per (t,j) {cos,sin}

__device__ __forceinline__ uint32_t f2h2(float lo, float hi) {
    __half2 h = __floats2half2_rn(lo, hi);
    return *(uint32_t*)&h;
}

__device__ __forceinline__ void mma_f16(float* d, const uint32_t* a, const uint32_t* b) {
    asm volatile(
        "mma.sync.aligned.m16n8k16.row.col.f32.f16.f16.f32 "
        "{%0,%1,%2,%3}, {%4,%5,%6,%7}, {%8,%9}, {%0,%1,%2,%3};"
        : "+f"(d[0]), "+f"(d[1]), "+f"(d[2]), "+f"(d[3])
        : "r"(a[0]), "r"(a[1]), "r"(a[2]), "r"(a[3]), "r"(b[0]), "r"(b[1]));
}

__device__ __forceinline__ void cp16(uint32_t saddr, const void* gptr) {
    asm volatile("cp.async.cg.shared.global [%0], [%1], 16;" :: "r"(saddr), "l"(gptr));
}

// ---------------- merged prepass (one launch) ----------------
__device__ __forceinline__ void pack_x_body(const float* __restrict__ x, int id) {
    int lane = id & 31, kg = (id >> 5) & 127, mb = id >> 12;
    int r = lane >> 2, lc = lane & 3;
    const float* p = x + (size_t)(mb * 16 + r) * 2048 + kg * 16 + 2 * lc;
    float2 v00 = *(const float2*)(p);
    float2 v01 = *(const float2*)(p + 8);
    float2 v10 = *(const float2*)(p + 8 * 2048);
    float2 v11 = *(const float2*)(p + 8 * 2048 + 8);
    g_x4[id] = make_uint4(f2h2(v00.x, v00.y), f2h2(v10.x, v10.y),
                          f2h2(v01.x, v01.y), f2h2(v11.x, v11.y));
}

__device__ __forceinline__ void pack_w_body(const float* __restrict__ w, uint4* __restrict__ out4,
                                            int nsh, int Ntot, int noff, int id) {
    int Nsrc = 1 << nsh;
    int lane = id & 31;
    int npl = (id >> 5) & ((Nsrc >> 4) - 1);
    int kg = id >> (nsh + 1);
    int r = lane >> 2, lc = lane & 3;
    const float* p = w + (size_t)(kg * 16 + 2 * lc) * Nsrc + npl * 16 + r;
    float a0 = p[0],        a1 = p[Nsrc];
    float a2 = p[8 * Nsrc], a3 = p[9 * Nsrc];
    float b0 = p[8],        b1 = p[Nsrc + 8];
    float b2 = p[8 * Nsrc + 8], b3 = p[9 * Nsrc + 8];
    out4[((size_t)kg * (Ntot >> 4) + (noff >> 4) + npl) * 32 + lane] =
        make_uint4(f2h2(a0, a1), f2h2(a2, a3), f2h2(b0, b1), f2h2(b2, b3));
}

// block ranges: [0,4096) x | [4096,6144) wq | [6144,7168) wk | [7168,8192) wv
//               [8192,10240) wo | [10240,10752) rope table
__global__ void prepack_kernel(const float* __restrict__ x,
                               const float* __restrict__ wq, const float* __restrict__ wk,
                               const float* __restrict__ wv, const float* __restrict__ wo) {
    int bid = blockIdx.x, tid = threadIdx.x;
    if (bid < 4096) {
        pack_x_body(x, bid * 256 + tid);
    } else if (bid < 6144) {
        pack_w_body(wq, g_wqkv4, 11, NCAT, 0,    (bid - 4096) * 256 + tid);
    } else if (bid < 7168) {
        pack_w_body(wk, g_wqkv4, 10, NCAT, 2048, (bid - 6144) * 256 + tid);
    } else if (bid < 8192) {
        pack_w_body(wv, g_wqkv4, 10, NCAT, 3072, (bid - 7168) * 256 + tid);
    } else if (bid < 10240) {
        pack_w_body(wo, g_wo4, 11, EE, 0,        (bid - 8192) * 256 + tid);
    } else {
        int i = (bid - 10240) * 256 + tid;      // < TT*64
        int j = i & 63, t = i >> 6;
        float inv = exp2f(-0.20762050593045952f * (float)j);  // 10000^(-j/64)
        float s, c;
        sincosf((float)t * inv, &s, &c);
        g_rope[i] = make_float2(c, s);
    }
}

// ---------------- 2-stage pipelined fp16 GEMM on pre-packed operands ----------------
// EPI: 0 plain fp32 store | 5 fused QKV epilogue (Q->g_q4, K->g_kx, V->g_vf)
template<int EPI>
__global__ __launch_bounds__(256, 2)
void gemm_kernel(const uint4* __restrict__ A4, const uint4* __restrict__ B4,
                 void* __restrict__ Cout, int M, int N, int K) {
    extern __shared__ uint32_t smu[];
    uint4* As4 = (uint4*)smu;                    // [2][1024] uint4 (16KB/stage)
    uint4* Bs4 = As4 + 2 * 1024;                 // [2][1024] uint4 (16KB/stage)

    const int tid  = threadIdx.x;
    const int brow = blockIdx.y * 128;
    const int bcol = blockIdx.x * 128;
    const int lane = tid & 31, warp = tid >> 5;
    const int wr = warp >> 2, wc = warp & 3;
    const int n_base = wc * 32;
    const int lr = lane >> 2, lc = lane & 3;
    const int KG16 = K >> 4;

    float acc[4][4][4];
#pragma unroll
    for (int mt = 0; mt < 4; mt++)
#pragma unroll
        for (int nt = 0; nt < 4; nt++)
#pragma unroll
            for (int i = 0; i < 4; i++) acc[mt][nt][i] = 0.f;

    const uint32_t as_base = (uint32_t)__cvta_generic_to_shared(As4);
    const uint32_t bs_base = (uint32_t)__cvta_generic_to_shared(Bs4);

#define LOAD_TILE(K0, BUF)                                                              \
    {                                                                                   \
        const int kg0 = (K0) >> 4;                                                      \
        _Pragma("unroll")                                                               \
        for (int i = 0; i < 4; i++) {                                                   \
            int id = tid + i * 256;                                                     \
            int mb = id >> 7, sub = id & 127;                                           \
            cp16(as_base + ((BUF) * 1024 + mb * 128 + sub) * 16,                        \
                 A4 + ((size_t)((brow >> 4) + mb) * KG16 + kg0 + (sub >> 5)) * 32       \
                    + (sub & 31));                                                      \
            int kgl = id >> 8, off = id & 255;                                          \
            cp16(bs_base + ((BUF) * 1024 + kgl * 256 + off) * 16,                       \
                 B4 + ((size_t)(kg0 + kgl) * (N >> 4) + (bcol >> 4)) * 32 + off);       \
        }                                                                               \
        asm volatile("cp.async.commit_group;");                                         \
    }

    const int NIT = K >> 6;     // BK=64
    LOAD_TILE(0, 0);

    for (int it = 0; it < NIT; it++) {
        if (it + 1 < NIT) {
            LOAD_TILE((it + 1) << 6, (it + 1) & 1);
            asm volatile("cp.async.wait_group 1;");
        } else {
            asm volatile("cp.async.wait_group 0;");
        }
        __syncthreads();

        const uint4* Ab = As4 + (it & 1) * 1024;
        const uint4* Bb = Bs4 + (it & 1) * 1024;
#pragma unroll
        for (int ks = 0; ks < 4; ks++) {
            uint4 afr[4], bfr4[2];
#pragma unroll
            for (int mt = 0; mt < 4; mt++)
                afr[mt] = Ab[(wr * 4 + mt) * 128 + ks * 32 + lane];
#pragma unroll
            for (int i = 0; i < 2; i++)
                bfr4[i] = Bb[ks * 256 + (wc * 2 + i) * 32 + lane];
#pragma unroll
            for (int mt = 0; mt < 4; mt++) {
                mma_f16(acc[mt][0], &afr[mt].x, &bfr4[0].x);
                mma_f16(acc[mt][1], &afr[mt].x, &bfr4[0].z);
                mma_f16(acc[mt][2], &afr[mt].x, &bfr4[1].x);
                mma_f16(acc[mt][3], &afr[mt].x, &bfr4[1].z);
            }
        }
        __syncthreads();
    }

    // ---------------- epilogue ----------------
#pragma unroll
    for (int mt = 0; mt < 4; mt++)
#pragma unroll
        for (int nt = 0; nt < 4; nt++) {
            int row = brow + wr * 64 + mt * 16 + lr;
            int col = bcol + n_base + nt * 8 + 2 * lc;
            float c0 = acc[mt][nt][0], c1 = acc[mt][nt][1];
            float c2 = acc[mt][nt][2], c3 = acc[mt][nt][3];
            if (EPI == 0) {
                float* C = (float*)Cout;
                *(float2*)(C + (size_t)row * N + col)       = make_float2(c0, c1);
                *(float2*)(C + (size_t)(row + 8) * N + col) = make_float2(c2, c3);
            } else {
                int b = row >> 11, t = row & (TT - 1);
                if (col < 2048) {
                    // Q: rope + scale -> packed-A fp16 fragment layout (g_q4)
                    int h = col >> 7, j = (col & 127) >> 1;
                    float2 r1 = g_rope[t * 64 + j];
                    float2 r2 = g_rope[(t + 8) * 64 + j];
                    float va = (c0 * r1.x - c1 * r1.y) * SCALE;   // (t,   j)
                    float vb = (c1 * r1.x + c0 * r1.y) * SCALE;   // (t,   j+64)
                    float vc = (c2 * r2.x - c3 * r2.y) * SCALE;   // (t+8, j)
                    float vd = (c3 * r2.x + c2 * r2.y) * SCALE;   // (t+8, j+64)
                    __half* W = (__half*)g_q4 + (size_t)(b * HH + h) * 262144;
#pragma unroll
                    for (int e = 0; e < 4; e++) {
                        int tt = (e < 2) ? t : t + 8;
                        int d  = (e & 1) ? j + 64 : j;
                        float val = (e == 0) ? va : (e == 1) ? vb : (e == 2) ? vc : vd;
                        int mblk = tt >> 4, rr = tt & 7, m8 = (tt >> 3) & 1;
                        int kg = d >> 4, dd = d & 15;
                        int idx = (((mblk * 8 + kg) * 32) + rr * 4 + ((dd >> 1) & 3)) * 8
                                  + (m8 + 2 * (dd >> 3)) * 2 + (dd & 1);
                        W[idx] = __float2half_rn(val);
                    }
                } else if (col < 3072) {
                    // K: rope -> packed fp16 B-frag pair layout (g_kx)
                    int colk = col - 2048;
                    int h = colk >> 7, j = (colk & 127) >> 1;
                    float2 r1 = g_rope[t * 64 + j];
                    float2 r2 = g_rope[(t + 8) * 64 + j];
                    float va = c0 * r1.x - c1 * r1.y;
                    float vb = c1 * r1.x + c0 * r1.y;
                    float vc = c2 * r2.x - c3 * r2.y;
                    float vd = c3 * r2.x + c2 * r2.y;
                    __half* W = (__half*)g_kx + (size_t)(b * HKV + h) * NT32 * 4096;
#pragma unroll
                    for (int e = 0; e < 4; e++) {
                        int tt = (e < 2) ? t : t + 8;
                        int d  = (e & 1) ? j + 64 : j;
                        float val = (e == 0) ? va : (e == 1) ? vb : (e == 2) ? vc : vd;
                        int tile = tt >> 5, s = tt & 31;
                        int sp = s >> 4, rr = s & 7, s8 = (s >> 3) & 1;
                        int kg = d >> 4, dd = d & 15;
                        int idx = tile * 4096
                                  + (((kg * 2 + sp) * 32) + rr * 4 + ((dd >> 1) & 3)) * 8
                                  + s8 * 4 + (dd >> 3) * 2 + (dd & 1);
                        W[idx] = __float2half_rn(val);
                    }
                } else {
                    // V: packed fp16 B-frag pair layout (g_vf); n-dim = d, k-dim = s
                    int colv = col - 3072;
                    int h = colv >> 7, d = colv & 127;
                    __half* W = (__half*)g_vf + (size_t)(b * HKV + h) * NT32 * 4096;
#pragma unroll
                    for (int e = 0; e < 4; e++) {
                        int tt = (e < 2) ? t : t + 8;
                        int dd = d + (e & 1);
                        float val = (e == 0) ? c0 : (e == 1) ? c1 : (e == 2) ? c2 : c3;
                        int tile = tt >> 5, s = tt & 31;
                        int ks = s >> 4, ss = s & 15;
                        int np = dd >> 4, rv = dd & 7, d8 = (dd >> 3) & 1;
                        int idx = tile * 4096
                                  + ((ks * 8 + np) * 32 + rv * 4 + ((ss >> 1) & 3)) * 8
                                  + d8 * 4 + ((ss >> 3) & 1) * 2 + (ss & 1);
                        W[idx] = __float2half_rn(val);
                    }
                }
            }
        }
}

// ---------------- Tensor-core flash attention (fp16 mma, causal) ----------------
// grid: (T/128, H, B); 256 threads (8 warps), 2 CTAs/SM, heavy tiles first.
// 64-row KV load granularity (2 sub-tiles of 32 per load) halves sync/wait count.
__global__ __launch_bounds__(256, 2)
void flash_kernel(const uint4* __restrict__ Q4, const uint32_t* __restrict__ KXg,
                  const uint32_t* __restrict__ VFg, uint4* __restrict__ Attn4) {
    extern __shared__ uint32_t smu[];
    uint32_t* KX = smu;                    // 2 x 4096  (64-row K tile, 16KB each)
    uint32_t* VF = smu + 8192;             // 2 x 4096  (64-row V tile)
    uint32_t* Ps = smu + 16384;            // 128 x PS_ST (half2 P)

    const int tid = threadIdx.x;
    const int qt = gridDim.x - 1 - blockIdx.x;   // heavy (large-qt) blocks first
    const int h = blockIdx.y, b = blockIdx.z;
    const int q0 = qt * QTILE;
    const int hkv = h & (HKV - 1);
    const int warp = tid >> 5, lane = tid & 31;
    const int lr = lane >> 2, lc = lane & 3;
    const int m0 = warp * 16;
    const int ra = m0 + lr, rb = ra + 8;
    const int grow_a = q0 + ra, grow_b = q0 + rb;

    // g_q4: 32768 uint4 per (b,h) = 128 mblk x 8 kg x 32 lanes
    const uint4*    Qb = Q4 + (size_t)(b * HH + h) * 32768 + (size_t)(qt * 8 + warp) * 256;
    const uint32_t* Kt = KXg + (size_t)(b * HKV + hkv) * NT32 * 2048;
    const uint32_t* Vt = VFg + (size_t)(b * HKV + hkv) * NT32 * 2048;

    const uint32_t kx_base = (uint32_t)__cvta_generic_to_shared(KX);
    const uint32_t vf_base = (uint32_t)__cvta_generic_to_shared(VF);

// load one 64-row KV tile (= two consecutive 32-row packed tiles, contiguous)
#define KV_ISSUE(KT64, BUF)                                                     \
    {                                                                           \
        _Pragma("unroll")                                                       \
        for (int i = 0; i < 4; i++) {                                           \
            int id = tid + i * 256;                                             \
            cp16(kx_base + ((BUF) * 4096 + id * 4) * 4,                         \
                 Kt + (size_t)(KT64) * 4096 + id * 4);                          \
            cp16(vf_base + ((BUF) * 4096 + id * 4) * 4,                         \
                 Vt + (size_t)(KT64) * 4096 + id * 4);                          \
        }                                                                       \
        asm volatile("cp.async.commit_group;");                                 \
    }

    const int nkt64 = 2 * (qt + 1);
    KV_ISSUE(0, 0);

    float O[16][4];
#pragma unroll
    for (int nb = 0; nb < 16; nb++)
#pragma unroll
        for (int i = 0; i < 4; i++) O[nb][i] = 0.f;
    float m_a = -1e30f, m_b = -1e30f, l_a = 0.f, l_b = 0.f;

    for (int kt64 = 0; kt64 < nkt64; kt64++) {
        asm volatile("cp.async.wait_group 0;");
        __syncthreads();
        if (kt64 + 1 < nkt64) KV_ISSUE(kt64 + 1, (kt64 + 1) & 1);

#pragma unroll
        for (int half = 0; half < 2; half++) {
            const int kts = kt64 * 2 + half;         // 32-row sub-tile index
            const uint4* Kb4 = (const uint4*)(KX + (kt64 & 1) * 4096) + half * 512;
            const uint4* Vb4 = (const uint4*)(VF + (kt64 & 1) * 4096) + half * 512;

            // ---- S = Q @ K^T (fp16 k16, 8 k-steps over D=128) ----
            float S[4][4];
#pragma unroll
            for (int nb = 0; nb < 4; nb++)
#pragma unroll
                for (int i = 0; i < 4; i++) S[nb][i] = 0.f;

#pragma unroll
            for (int ks = 0; ks < 8; ks++) {
                uint4 qf  = Qb[ks * 32 + lane];
                uint4 kf0 = Kb4[(ks * 2 + 0) * 32 + lane];
                uint4 kf1 = Kb4[(ks * 2 + 1) * 32 + lane];
                mma_f16(S[0], &qf.x, &kf0.x);
                mma_f16(S[1], &qf.x, &kf0.z);
                mma_f16(S[2], &qf.x, &kf1.x);
                mma_f16(S[3], &qf.x, &kf1.z);
            }

            // ---- causal mask (only diagonal-overlapping sub-tiles) ----
            const int s0 = kts * KT32;
            if (kts >= 4 * qt) {
#pragma unroll
                for (int nb = 0; nb < 4; nb++) {
                    int col = s0 + nb * 8 + 2 * lc;
                    if (col     > grow_a) S[nb][0] = -1e30f;
                    if (col + 1 > grow_a) S[nb][1] = -1e30f;
                    if (col     > grow_b) S[nb][2] = -1e30f;
                    if (col + 1 > grow_b) S[nb][3] = -1e30f;
                }
            }

            // ---- online softmax (MUFU exp) ----
            float mxa = m_a, mxb = m_b;
#pragma unroll
            for (int nb = 0; nb < 4; nb++) {
                mxa = fmaxf(mxa, fmaxf(S[nb][0], S[nb][1]));
                mxb = fmaxf(mxb, fmaxf(S[nb][2], S[nb][3]));
            }
            mxa = fmaxf(mxa, __shfl_xor_sync(0xffffffffu, mxa, 1));
            mxa = fmaxf(mxa, __shfl_xor_sync(0xffffffffu, mxa, 2));
            mxb = fmaxf(mxb, __shfl_xor_sync(0xffffffffu, mxb, 1));
            mxb = fmaxf(mxb, __shfl_xor_sync(0xffffffffu, mxb, 2));

            float corr_a = __expf(m_a - mxa);
            float corr_b = __expf(m_b - mxb);
            m_a = mxa; m_b = mxb;

            float suma = 0.f, sumb = 0.f;
#pragma unroll
            for (int nb = 0; nb < 4; nb++) {
                float p0 = __expf(S[nb][0] - mxa);
                float p1 = __expf(S[nb][1] - mxa);
                float p2 = __expf(S[nb][2] - mxb);
                float p3 = __expf(S[nb][3] - mxb);
                suma += p0 + p1;
                sumb += p2 + p3;
                Ps[ra * PS_ST + nb * 4 + lc] = f2h2(p0, p1);
                Ps[rb * PS_ST + nb * 4 + lc] = f2h2(p2, p3);
            }
            suma += __shfl_xor_sync(0xffffffffu, suma, 1);
            suma += __shfl_xor_sync(0xffffffffu, suma, 2);
            sumb += __shfl_xor_sync(0xffffffffu, sumb, 1);
            sumb += __shfl_xor_sync(0xffffffffu, sumb, 2);
            l_a = l_a * corr_a + suma;
            l_b = l_b * corr_b + sumb;

#pragma unroll
            for (int nb = 0; nb < 16; nb++) {
                O[nb][0] *= corr_a; O[nb][1] *= corr_a;
                O[nb][2] *= corr_b; O[nb][3] *= corr_b;
            }
            __syncwarp();    // P is warp-private (rows of this warp only)

            // ---- O += P @ V (fp16 k16, 2 k-steps over s=32) ----
#pragma unroll
            for (int ks = 0; ks < 2; ks++) {
                uint32_t a[4] = { Ps[ra * PS_ST + ks * 8 + lc],
                                  Ps[rb * PS_ST + ks * 8 + lc],
                                  Ps[ra * PS_ST + ks * 8 + lc + 4],
                                  Ps[rb * PS_ST + ks * 8 + lc + 4] };
#pragma unroll
                for (int np = 0; np < 8; np++) {
                    uint4 vv = Vb4[(ks * 8 + np) * 32 + lane];
                    mma_f16(O[2 * np],     a, &vv.x);
                    mma_f16(O[2 * np + 1], a, &vv.z);
                }
            }
        }
    }

    // ---- epilogue: normalize + write packed-A fp16 attn ----
    float inva = 1.0f / l_a, invb = 1.0f / l_b;
    uint32_t* attnW = (uint32_t*)Attn4;
    const int mblk = b * 128 + qt * 8 + warp;
#pragma unroll
    for (int nb = 0; nb < 16; nb++) {
        int kg  = h * 8 + (nb >> 1);
        int khi = nb & 1;
        size_t u4i = ((size_t)mblk * 128 + kg) * 32 + lr * 4 + lc;
        attnW[u4i * 4 + 0 + 2 * khi] = f2h2(O[nb][0] * inva, O[nb][1] * inva);
        attnW[u4i * 4 + 1 + 2 * khi] = f2h2(O[nb][2] * invb, O[nb][3] * invb);
    }
}

// ---------------- launch ----------------
extern "C" void kernel_launch(void* const* d_in, const int* in_sizes, int n_in,
                              void* d_out, int out_size) {
    const float* x  = (const float*)d_in[0];
    const float* wq = (const float*)d_in[2];
    const float* wk = (const float*)d_in[3];
    const float* wv = (const float*)d_in[4];
    const float* wo = (const float*)d_in[5];
    float* out = (float*)d_out;

    uint4 *x4, *wqkv4, *wo4, *q4, *attn4;
    uint32_t *kx, *vf;
    cudaGetSymbolAddress((void**)&x4,    g_x4);
    cudaGetSymbolAddress((void**)&wqkv4, g_wqkv4);
    cudaGetSymbolAddress((void**)&wo4,   g_wo4);
    cudaGetSymbolAddress((void**)&q4,    g_q4);
    cudaGetSymbolAddress((void**)&kx,    g_kx);
    cudaGetSymbolAddress((void**)&vf,    g_vf);
    cudaGetSymbolAddress((void**)&attn4, g_attn4);

    const int M = BB * TT;    // 4096
    const size_t gsmem = 65536;   // 2 stages x (16KB A + 16KB B)

    cudaFuncSetAttribute(gemm_kernel<0>, cudaFuncAttributeMaxDynamicSharedMemorySize, (int)gsmem);
    cudaFuncSetAttribute(gemm_kernel<5>, cudaFuncAttributeMaxDynamicSharedMemorySize, (int)gsmem);

    // single merged prepass: x/w packing + rope table (one launch)
    prepack_kernel<<<10752, 256>>>(x, wq, wk, wv, wo);

    // Fused QKV projection (one launch, epilogue dispatched by column block)
    gemm_kernel<5><<<dim3(NCAT/128, M/128), 256, gsmem>>>(x4, wqkv4, nullptr, M, NCAT, EE);

    // Flash attention (74 KB dynamic smem, 2 CTAs/SM)
    {
        size_t smem = (16384 + 128 * PS_ST) * sizeof(uint32_t);  // 75776 B
        cudaFuncSetAttribute(flash_kernel, cudaFuncAttributeMaxDynamicSharedMemorySize, (int)smem);
        flash_kernel<<<dim3(TT/QTILE, HH, BB), 256, smem>>>(q4, kx, vf, attn4);
    }

    // Output projection (packed fp16 attn, plain fp32 store)
    gemm_kernel<0><<<dim3(EE/128, M/128), 256, gsmem>>>(attn4, wo4, out, M, EE, EE);
}